// round 7
// baseline (speedup 1.0000x reference)
#include <cuda_runtime.h>

static constexpr int N = 100000;
static constexpr int E = 1600000;
static constexpr int SCAN_B = 512;
static constexpr int NB_SCAN = (N + SCAN_B - 1) / SCAN_B;   // 196
static constexpr int NB_REORDER = E / 256;                  // 6250
static constexpr int NB_GEMM1 = N / 32;                     // 3125

// ---- device-global scratch ----
__device__ float g_wdeg[N];     // sum of edge weights into node (memset 0)
__device__ float g_dinv[N];
__device__ int   g_cnt[N];      // in-degree counts (memset 0)
__device__ int   g_scan[N];     // inclusive scan of cnt
__device__ int   g_rs[N];       // CSR row start (exclusive prefix)
__device__ int   g_cur[N];      // reorder cursors
__device__ int   g_bsum[NB_SCAN];
__device__ int   g_boff[NB_SCAN];
__device__ int2  g_edge[E];     // bucketed edges: {src, w*dinv[src] as bits}
__device__ float g_y1[N * 64];  // x @ W1 (raw, no dinv)
__device__ float g_h [N * 64];
__device__ float g_y2[N * 32];  // h @ W2 (raw)

// ---- count + weighted degree ----
__global__ void k_prep(const int* __restrict__ ei, const float* __restrict__ ew) {
    int e = blockIdx.x * blockDim.x + threadIdx.x;
    if (e >= E) return;
    int d = ei[E + e];
    if ((unsigned)d >= (unsigned)N) d = 0;
    atomicAdd(&g_wdeg[d], ew[e]);
    atomicAdd(&g_cnt[d], 1);
}

// ---- scan stage 1: per-block inclusive scan (warp shuffles) ----
__global__ void __launch_bounds__(SCAN_B) k_scan_block() {
    __shared__ int wsum[16];
    int t = threadIdx.x, lane = t & 31, wid = t >> 5;
    int g = blockIdx.x * SCAN_B + t;
    int v = (g < N) ? g_cnt[g] : 0;
    int s = v;
    #pragma unroll
    for (int o = 1; o < 32; o <<= 1) {
        int n = __shfl_up_sync(0xffffffffu, s, o);
        if (lane >= o) s += n;
    }
    if (lane == 31) wsum[wid] = s;
    __syncthreads();
    if (wid == 0) {
        int ws = (lane < 16) ? wsum[lane] : 0;
        #pragma unroll
        for (int o = 1; o < 16; o <<= 1) {
            int n = __shfl_up_sync(0xffffffffu, ws, o);
            if (lane >= o) ws += n;
        }
        if (lane < 16) wsum[lane] = ws;
    }
    __syncthreads();
    int off = wid ? wsum[wid - 1] : 0;
    s += off;
    if (g < N) g_scan[g] = s;
    if (t == SCAN_B - 1) g_bsum[blockIdx.x] = s;
}

// ---- scan stage 2: exclusive scan of 196 block sums (one block) ----
__global__ void __launch_bounds__(256) k_scan_bsum() {
    __shared__ int wsum[8];
    int t = threadIdx.x, lane = t & 31, wid = t >> 5;
    int v = (t < NB_SCAN) ? g_bsum[t] : 0;
    int s = v;
    #pragma unroll
    for (int o = 1; o < 32; o <<= 1) {
        int n = __shfl_up_sync(0xffffffffu, s, o);
        if (lane >= o) s += n;
    }
    if (lane == 31) wsum[wid] = s;
    __syncthreads();
    if (wid == 0) {
        int ws = (lane < 8) ? wsum[lane] : 0;
        #pragma unroll
        for (int o = 1; o < 8; o <<= 1) {
            int n = __shfl_up_sync(0xffffffffu, ws, o);
            if (lane >= o) ws += n;
        }
        if (lane < 8) wsum[lane] = ws;
    }
    __syncthreads();
    int off = wid ? wsum[wid - 1] : 0;
    if (t < NB_SCAN) g_boff[t] = s + off - v;   // exclusive
}

// ---- scan stage 3: row starts, cursors, dinv ----
__global__ void k_scan_fix() {
    int i = blockIdx.x * blockDim.x + threadIdx.x;
    if (i >= N) return;
    int incl = g_scan[i] + g_boff[i / SCAN_B];
    int start = incl - g_cnt[i];
    g_rs[i]  = start;
    g_cur[i] = start;
    g_dinv[i] = rsqrtf(1.0f + g_wdeg[i]);   // self loop contributes 1
}

// ---- fused: reorder (blocks [0,NB_REORDER)) + gemm1 (rest), one launch.
//      reorder is atomic/latency-bound; gemm1 is FMA-bound; they overlap. ----
__global__ void __launch_bounds__(256) k_reorder_gemm1(
        const int* __restrict__ ei, const float* __restrict__ ew,
        const float* __restrict__ X, const float* __restrict__ W) {
    __shared__ float Ws[64 * 64];              // 16 KB
    __shared__ float Xs[32][68];               // 8.5 KB

    if (blockIdx.x < NB_REORDER) {
        // -------- bucket edges by destination, bake dinv[src] into weight ----
        int e = blockIdx.x * 256 + threadIdx.x;
        int s = ei[e];
        int d = ei[E + e];
        if ((unsigned)s >= (unsigned)N) s = 0;
        if ((unsigned)d >= (unsigned)N) d = 0;
        float wp = ew[e] * __ldg(&g_dinv[s]);
        int pos = atomicAdd(&g_cur[d], 1);
        g_edge[pos] = make_int2(s, __float_as_int(wp));
        return;
    }

    // -------- gemm1: y1 = x @ W1 (raw). 32 nodes/block, 2 nodes/thread ----
    int bid = blockIdx.x - NB_REORDER;
    int tid = threadIdx.x;
    {
        const float4* Wg = (const float4*)W;
        float4* Ws4 = (float4*)Ws;
        #pragma unroll
        for (int i = tid; i < 64 * 64 / 4; i += 256) Ws4[i] = Wg[i];
    }
    int nb = bid * 32;
    #pragma unroll
    for (int i = tid; i < 32 * 16; i += 256) {
        int node = i >> 4, k4 = i & 15;
        *((float4*)&Xs[node][k4 * 4]) = ((const float4*)(X + (nb + node) * 64))[k4];
    }
    __syncthreads();

    int tx = tid & 15, ty = tid >> 4;          // ty in 0..15
    float4 a0 = {0,0,0,0}, a1 = {0,0,0,0};
    #pragma unroll
    for (int k4 = 0; k4 < 16; k4++) {
        float4 xv0 = *((const float4*)&Xs[ty][k4 * 4]);
        float4 xv1 = *((const float4*)&Xs[ty + 16][k4 * 4]);
        #pragma unroll
        for (int kk = 0; kk < 4; kk++) {
            float4 w4 = *((const float4*)&Ws[(k4 * 4 + kk) * 64 + tx * 4]);
            float x0 = (&xv0.x)[kk], x1 = (&xv1.x)[kk];
            a0.x = fmaf(x0, w4.x, a0.x); a0.y = fmaf(x0, w4.y, a0.y);
            a0.z = fmaf(x0, w4.z, a0.z); a0.w = fmaf(x0, w4.w, a0.w);
            a1.x = fmaf(x1, w4.x, a1.x); a1.y = fmaf(x1, w4.y, a1.y);
            a1.z = fmaf(x1, w4.z, a1.z); a1.w = fmaf(x1, w4.w, a1.w);
        }
    }
    *((float4*)&g_y1[(nb + ty) * 64 + tx * 4])      = a0;
    *((float4*)&g_y1[(nb + ty + 16) * 64 + tx * 4]) = a1;
}

// ---- layer-1 aggregate (warp per node):
//      h = relu(dinv*(dinv*y1[d] + sum w'*y1[s]) + b1) ----
__global__ void __launch_bounds__(256) k_agg1(const float* __restrict__ b1) {
    int warp = (blockIdx.x * 256 + threadIdx.x) >> 5;
    if (warp >= N) return;
    int lane = threadIdx.x & 31;
    int d = warp;
    int beg = g_rs[d], end = beg + g_cnt[d];
    float di = g_dinv[d];
    float2 self = *(const float2*)&g_y1[d * 64 + lane * 2];
    float2 acc;                                 // di * self-term
    acc.x = di * self.x; acc.y = di * self.y;
    int j = beg;
    for (; j + 3 < end; j += 4) {
        int2 e0 = __ldg(&g_edge[j]),     e1 = __ldg(&g_edge[j + 1]);
        int2 e2 = __ldg(&g_edge[j + 2]), e3 = __ldg(&g_edge[j + 3]);
        float2 v0 = __ldg((const float2*)&g_y1[e0.x * 64 + lane * 2]);
        float2 v1 = __ldg((const float2*)&g_y1[e1.x * 64 + lane * 2]);
        float2 v2 = __ldg((const float2*)&g_y1[e2.x * 64 + lane * 2]);
        float2 v3 = __ldg((const float2*)&g_y1[e3.x * 64 + lane * 2]);
        float w0 = __int_as_float(e0.y), w1 = __int_as_float(e1.y);
        float w2 = __int_as_float(e2.y), w3 = __int_as_float(e3.y);
        acc.x = fmaf(w0, v0.x, acc.x); acc.y = fmaf(w0, v0.y, acc.y);
        acc.x = fmaf(w1, v1.x, acc.x); acc.y = fmaf(w1, v1.y, acc.y);
        acc.x = fmaf(w2, v2.x, acc.x); acc.y = fmaf(w2, v2.y, acc.y);
        acc.x = fmaf(w3, v3.x, acc.x); acc.y = fmaf(w3, v3.y, acc.y);
    }
    for (; j < end; j++) {
        int2 e = __ldg(&g_edge[j]);
        float wt = __int_as_float(e.y);
        float2 v = __ldg((const float2*)&g_y1[e.x * 64 + lane * 2]);
        acc.x = fmaf(wt, v.x, acc.x); acc.y = fmaf(wt, v.y, acc.y);
    }
    float2 h;
    h.x = fmaxf(fmaf(di, acc.x, __ldg(&b1[lane * 2])), 0.0f);
    h.y = fmaxf(fmaf(di, acc.y, __ldg(&b1[lane * 2 + 1])), 0.0f);
    *((float2*)&g_h[d * 64 + lane * 2]) = h;
}

// ---- layer-2 GEMM: y2 = h @ W2 (raw) ----
__global__ void __launch_bounds__(128) k_gemm2(const float* __restrict__ W2) {
    constexpr int TX = 8, TY = 16, NPB = 32;
    __shared__ float Ws[64 * 32];
    __shared__ float Xs[NPB][68];
    int tid = threadIdx.y * TX + threadIdx.x;
    {
        const float4* Wg = (const float4*)W2;
        float4* Ws4 = (float4*)Ws;
        #pragma unroll
        for (int i = tid; i < 64 * 32 / 4; i += 128) Ws4[i] = Wg[i];
    }
    int nb = blockIdx.x * NPB;
    #pragma unroll
    for (int i = tid; i < NPB * 16; i += 128) {
        int node = i >> 4, k4 = i & 15;
        *((float4*)&Xs[node][k4 * 4]) = ((const float4*)&g_h[(nb + node) * 64])[k4];
    }
    __syncthreads();

    int tx = threadIdx.x, ty = threadIdx.y;
    float4 a0 = {0,0,0,0}, a1 = {0,0,0,0};
    #pragma unroll
    for (int k = 0; k < 64; k++) {
        float4 w4 = *((const float4*)&Ws[k * 32 + tx * 4]);
        float x0 = Xs[ty][k], x1 = Xs[ty + TY][k];
        a0.x = fmaf(x0, w4.x, a0.x); a0.y = fmaf(x0, w4.y, a0.y);
        a0.z = fmaf(x0, w4.z, a0.z); a0.w = fmaf(x0, w4.w, a0.w);
        a1.x = fmaf(x1, w4.x, a1.x); a1.y = fmaf(x1, w4.y, a1.y);
        a1.z = fmaf(x1, w4.z, a1.z); a1.w = fmaf(x1, w4.w, a1.w);
    }
    int n0 = nb + ty, n1 = nb + ty + TY;
    *((float4*)&g_y2[n0 * 32 + tx * 4]) = a0;
    *((float4*)&g_y2[n1 * 32 + tx * 4]) = a1;
}

// ---- layer-2 aggregate + epilogue: out = dinv*(dinv*y2[d] + sum w'*y2[s]) + b2 ----
__global__ void __launch_bounds__(256) k_agg2(const float* __restrict__ b2,
                                              float* __restrict__ out) {
    int warp = (blockIdx.x * 256 + threadIdx.x) >> 5;
    if (warp >= N) return;
    int lane = threadIdx.x & 31;
    int d = warp;
    int beg = g_rs[d], end = beg + g_cnt[d];
    float di = g_dinv[d];
    float acc = di * g_y2[d * 32 + lane];      // self loop
    int j = beg;
    for (; j + 3 < end; j += 4) {
        int2 e0 = __ldg(&g_edge[j]),     e1 = __ldg(&g_edge[j + 1]);
        int2 e2 = __ldg(&g_edge[j + 2]), e3 = __ldg(&g_edge[j + 3]);
        float v0 = __ldg(&g_y2[e0.x * 32 + lane]);
        float v1 = __ldg(&g_y2[e1.x * 32 + lane]);
        float v2 = __ldg(&g_y2[e2.x * 32 + lane]);
        float v3 = __ldg(&g_y2[e3.x * 32 + lane]);
        acc = fmaf(__int_as_float(e0.y), v0, acc);
        acc = fmaf(__int_as_float(e1.y), v1, acc);
        acc = fmaf(__int_as_float(e2.y), v2, acc);
        acc = fmaf(__int_as_float(e3.y), v3, acc);
    }
    for (; j < end; j++) {
        int2 e = __ldg(&g_edge[j]);
        acc = fmaf(__int_as_float(e.y), __ldg(&g_y2[e.x * 32 + lane]), acc);
    }
    out[d * 32 + lane] = fmaf(di, acc, b2[lane]);
}

extern "C" void kernel_launch(void* const* d_in, const int* in_sizes, int n_in,
                              void* d_out, int out_size) {
    const float* x  = (const float*)d_in[0];
    const int*   ei = (const int*)d_in[1];     // edge_index as int32
    const float* ew = (const float*)d_in[2];
    const float* W1 = (const float*)d_in[3];
    const float* b1 = (const float*)d_in[4];
    const float* W2 = (const float*)d_in[5];
    const float* b2 = (const float*)d_in[6];
    float* out = (float*)d_out;

    void* p_cnt = nullptr; void* p_wdeg = nullptr;
    cudaGetSymbolAddress(&p_cnt, g_cnt);
    cudaGetSymbolAddress(&p_wdeg, g_wdeg);
    cudaMemsetAsync(p_cnt, 0, N * sizeof(int));
    cudaMemsetAsync(p_wdeg, 0, N * sizeof(float));

    k_prep        <<<(E + 255) / 256, 256>>>(ei, ew);
    k_scan_block  <<<NB_SCAN, SCAN_B>>>();
    k_scan_bsum   <<<1, 256>>>();
    k_scan_fix    <<<(N + 255) / 256, 256>>>();
    k_reorder_gemm1<<<NB_REORDER + NB_GEMM1, 256>>>(ei, ew, x, W1);
    k_agg1        <<<(N * 32 + 255) / 256, 256>>>(b1);
    k_gemm2       <<<NB_GEMM1, dim3(8, 16)>>>(W2);
    k_agg2        <<<(N * 32 + 255) / 256, 256>>>(b2, out);
}

// round 8
// speedup vs baseline: 1.7285x; 1.7285x over previous
#include <cuda_runtime.h>

static constexpr int N = 100000;
static constexpr int E = 1600000;
static constexpr int SCAN_B = 512;
static constexpr int NB_SCAN = (N + SCAN_B - 1) / SCAN_B;   // 196

// ---- device-global scratch ----
__device__ unsigned long long g_cw[N];  // packed: count<<40 | wdeg*2^24 (memset 0)
__device__ float g_dinv[N];
__device__ int   g_cnt[N];      // in-degree counts (decoded)
__device__ int   g_scan[N];     // inclusive scan of cnt
__device__ int   g_rs[N];       // CSR row start (exclusive prefix)
__device__ int   g_cur[N];      // reorder cursors
__device__ int   g_bsum[NB_SCAN];
__device__ int   g_boff[NB_SCAN];
__device__ int2  g_edge[E];     // bucketed edges: {src, w as bits}
__device__ float g_y1[N * 64];  // dinv * (x @ W1)
__device__ float g_h [N * 64];
__device__ float g_y2[N * 32];  // dinv * (h @ W2)

// ---- count + weighted degree: one packed u64 atomic per edge, 4 edges/thread ----
__global__ void k_prep(const int* __restrict__ ei, const float* __restrict__ ew) {
    int t = blockIdx.x * blockDim.x + threadIdx.x;
    int e = t * 4;
    if (e >= E) return;
    int4   d4 = *((const int4*)(ei + E + e));
    float4 w4 = *((const float4*)(ew + e));
    #pragma unroll
    for (int k = 0; k < 4; k++) {
        int d = (&d4.x)[k];
        float w = (&w4.x)[k];
        if ((unsigned)d >= (unsigned)N) d = 0;
        unsigned long long v = (1ULL << 40) |
            (unsigned long long)(unsigned int)__float2uint_rn(w * 16777216.0f);
        atomicAdd(&g_cw[d], v);
    }
}

// ---- decode packed counts (needed before scan) ----
__global__ void k_decode() {
    int i = blockIdx.x * blockDim.x + threadIdx.x;
    if (i >= N) return;
    unsigned long long p = g_cw[i];
    int cnt = (int)(p >> 40);
    float wdeg = (float)(p & ((1ULL << 40) - 1)) * (1.0f / 16777216.0f);
    g_cnt[i] = cnt;
    g_dinv[i] = rsqrtf(1.0f + wdeg);   // self loop contributes 1
}

// ---- scan stage 1: per-block inclusive scan (warp shuffles) ----
__global__ void __launch_bounds__(SCAN_B) k_scan_block() {
    __shared__ int wsum[16];
    int t = threadIdx.x, lane = t & 31, wid = t >> 5;
    int g = blockIdx.x * SCAN_B + t;
    int v = (g < N) ? g_cnt[g] : 0;
    int s = v;
    #pragma unroll
    for (int o = 1; o < 32; o <<= 1) {
        int n = __shfl_up_sync(0xffffffffu, s, o);
        if (lane >= o) s += n;
    }
    if (lane == 31) wsum[wid] = s;
    __syncthreads();
    if (wid == 0) {
        int ws = (lane < 16) ? wsum[lane] : 0;
        #pragma unroll
        for (int o = 1; o < 16; o <<= 1) {
            int n = __shfl_up_sync(0xffffffffu, ws, o);
            if (lane >= o) ws += n;
        }
        if (lane < 16) wsum[lane] = ws;
    }
    __syncthreads();
    int off = wid ? wsum[wid - 1] : 0;
    s += off;
    if (g < N) g_scan[g] = s;
    if (t == SCAN_B - 1) g_bsum[blockIdx.x] = s;
}

// ---- scan stage 2: exclusive scan of 196 block sums (one block) ----
__global__ void __launch_bounds__(256) k_scan_bsum() {
    __shared__ int wsum[8];
    int t = threadIdx.x, lane = t & 31, wid = t >> 5;
    int v = (t < NB_SCAN) ? g_bsum[t] : 0;
    int s = v;
    #pragma unroll
    for (int o = 1; o < 32; o <<= 1) {
        int n = __shfl_up_sync(0xffffffffu, s, o);
        if (lane >= o) s += n;
    }
    if (lane == 31) wsum[wid] = s;
    __syncthreads();
    if (wid == 0) {
        int ws = (lane < 8) ? wsum[lane] : 0;
        #pragma unroll
        for (int o = 1; o < 8; o <<= 1) {
            int n = __shfl_up_sync(0xffffffffu, ws, o);
            if (lane >= o) ws += n;
        }
        if (lane < 8) wsum[lane] = ws;
    }
    __syncthreads();
    int off = wid ? wsum[wid - 1] : 0;
    if (t < NB_SCAN) g_boff[t] = s + off - v;   // exclusive
}

// ---- scan stage 3: row starts + cursors ----
__global__ void k_scan_fix() {
    int i = blockIdx.x * blockDim.x + threadIdx.x;
    if (i >= N) return;
    int incl = g_scan[i] + g_boff[i / SCAN_B];
    int start = incl - g_cnt[i];
    g_rs[i]  = start;
    g_cur[i] = start;
}

// ---- bucket edges by destination ----
__global__ void k_reorder(const int* __restrict__ ei, const float* __restrict__ ew) {
    int e = blockIdx.x * blockDim.x + threadIdx.x;
    if (e >= E) return;
    int s = ei[e];
    int d = ei[E + e];
    if ((unsigned)s >= (unsigned)N) s = 0;
    if ((unsigned)d >= (unsigned)N) d = 0;
    int pos = atomicAdd(&g_cur[d], 1);
    g_edge[pos] = make_int2(s, __float_as_int(ew[e]));
}

// ---- layer-1 GEMM: y1 = dinv * (x @ W1). 4 nodes/thread, float4 X reads ----
__global__ void __launch_bounds__(128) k_gemm1(const float* __restrict__ X,
                                               const float* __restrict__ W) {
    constexpr int TX = 16, NPB = 32;
    __shared__ float Ws[64 * 64];
    __shared__ float Xs[NPB][68];
    int tid = threadIdx.y * TX + threadIdx.x;
    {
        const float4* Wg = (const float4*)W;
        float4* Ws4 = (float4*)Ws;
        #pragma unroll
        for (int i = tid; i < 64 * 64 / 4; i += 128) Ws4[i] = Wg[i];
    }
    int nb = blockIdx.x * NPB;                 // N % 32 == 0
    #pragma unroll
    for (int i = tid; i < NPB * 16; i += 128) {
        int node = i >> 4, k4 = i & 15;
        *((float4*)&Xs[node][k4 * 4]) = ((const float4*)(X + (nb + node) * 64))[k4];
    }
    __syncthreads();

    int tx = threadIdx.x, ty = threadIdx.y;    // ty in 0..7
    float4 a0 = {0,0,0,0}, a1 = {0,0,0,0}, a2 = {0,0,0,0}, a3 = {0,0,0,0};
    #pragma unroll
    for (int k4 = 0; k4 < 16; k4++) {
        float4 xv0 = *((const float4*)&Xs[ty][k4 * 4]);
        float4 xv1 = *((const float4*)&Xs[ty + 8][k4 * 4]);
        float4 xv2 = *((const float4*)&Xs[ty + 16][k4 * 4]);
        float4 xv3 = *((const float4*)&Xs[ty + 24][k4 * 4]);
        #pragma unroll
        for (int kk = 0; kk < 4; kk++) {
            float4 w4 = *((const float4*)&Ws[(k4 * 4 + kk) * 64 + tx * 4]);
            float x0 = (&xv0.x)[kk], x1 = (&xv1.x)[kk];
            float x2 = (&xv2.x)[kk], x3 = (&xv3.x)[kk];
            a0.x = fmaf(x0, w4.x, a0.x); a0.y = fmaf(x0, w4.y, a0.y);
            a0.z = fmaf(x0, w4.z, a0.z); a0.w = fmaf(x0, w4.w, a0.w);
            a1.x = fmaf(x1, w4.x, a1.x); a1.y = fmaf(x1, w4.y, a1.y);
            a1.z = fmaf(x1, w4.z, a1.z); a1.w = fmaf(x1, w4.w, a1.w);
            a2.x = fmaf(x2, w4.x, a2.x); a2.y = fmaf(x2, w4.y, a2.y);
            a2.z = fmaf(x2, w4.z, a2.z); a2.w = fmaf(x2, w4.w, a2.w);
            a3.x = fmaf(x3, w4.x, a3.x); a3.y = fmaf(x3, w4.y, a3.y);
            a3.z = fmaf(x3, w4.z, a3.z); a3.w = fmaf(x3, w4.w, a3.w);
        }
    }
    #pragma unroll
    for (int m = 0; m < 4; m++) {
        int n = nb + ty + 8 * m;
        float sc = g_dinv[n];
        float4 a = (m == 0) ? a0 : (m == 1) ? a1 : (m == 2) ? a2 : a3;
        a.x *= sc; a.y *= sc; a.z *= sc; a.w *= sc;
        *((float4*)&g_y1[n * 64 + tx * 4]) = a;
    }
}

// ---- layer-1 aggregate (warp per node): h = relu(dinv*(y1[d] + sum w*y1[s]) + b1) ----
__global__ void __launch_bounds__(256) k_agg1(const float* __restrict__ b1) {
    int warp = (blockIdx.x * 256 + threadIdx.x) >> 5;
    if (warp >= N) return;
    int lane = threadIdx.x & 31;
    int d = warp;
    int beg = g_rs[d], end = beg + g_cnt[d];
    float2 acc = *(const float2*)&g_y1[d * 64 + lane * 2];   // self loop
    int j = beg;
    for (; j + 3 < end; j += 4) {
        int2 e0 = __ldg(&g_edge[j]),     e1 = __ldg(&g_edge[j + 1]);
        int2 e2 = __ldg(&g_edge[j + 2]), e3 = __ldg(&g_edge[j + 3]);
        float2 v0 = __ldg((const float2*)&g_y1[e0.x * 64 + lane * 2]);
        float2 v1 = __ldg((const float2*)&g_y1[e1.x * 64 + lane * 2]);
        float2 v2 = __ldg((const float2*)&g_y1[e2.x * 64 + lane * 2]);
        float2 v3 = __ldg((const float2*)&g_y1[e3.x * 64 + lane * 2]);
        float w0 = __int_as_float(e0.y), w1 = __int_as_float(e1.y);
        float w2 = __int_as_float(e2.y), w3 = __int_as_float(e3.y);
        acc.x = fmaf(w0, v0.x, acc.x); acc.y = fmaf(w0, v0.y, acc.y);
        acc.x = fmaf(w1, v1.x, acc.x); acc.y = fmaf(w1, v1.y, acc.y);
        acc.x = fmaf(w2, v2.x, acc.x); acc.y = fmaf(w2, v2.y, acc.y);
        acc.x = fmaf(w3, v3.x, acc.x); acc.y = fmaf(w3, v3.y, acc.y);
    }
    for (; j < end; j++) {
        int2 e = __ldg(&g_edge[j]);
        float w = __int_as_float(e.y);
        float2 v = __ldg((const float2*)&g_y1[e.x * 64 + lane * 2]);
        acc.x = fmaf(w, v.x, acc.x); acc.y = fmaf(w, v.y, acc.y);
    }
    float di = g_dinv[d];
    float2 h;
    h.x = fmaxf(fmaf(di, acc.x, __ldg(&b1[lane * 2])), 0.0f);
    h.y = fmaxf(fmaf(di, acc.y, __ldg(&b1[lane * 2 + 1])), 0.0f);
    *((float2*)&g_h[d * 64 + lane * 2]) = h;
}

// ---- layer-2 GEMM: y2 = dinv * (h @ W2) ----
__global__ void __launch_bounds__(128) k_gemm2(const float* __restrict__ W2) {
    constexpr int TX = 8, TY = 16, NPB = 32;
    __shared__ float Ws[64 * 32];
    __shared__ float Xs[NPB][68];
    int tid = threadIdx.y * TX + threadIdx.x;
    {
        const float4* Wg = (const float4*)W2;
        float4* Ws4 = (float4*)Ws;
        #pragma unroll
        for (int i = tid; i < 64 * 32 / 4; i += 128) Ws4[i] = Wg[i];
    }
    int nb = blockIdx.x * NPB;
    #pragma unroll
    for (int i = tid; i < NPB * 16; i += 128) {
        int node = i >> 4, k4 = i & 15;
        *((float4*)&Xs[node][k4 * 4]) = ((const float4*)&g_h[(nb + node) * 64])[k4];
    }
    __syncthreads();

    int tx = threadIdx.x, ty = threadIdx.y;
    float4 a0 = {0,0,0,0}, a1 = {0,0,0,0};
    #pragma unroll
    for (int k = 0; k < 64; k++) {
        float4 w4 = *((const float4*)&Ws[k * 32 + tx * 4]);
        float x0 = Xs[ty][k], x1 = Xs[ty + TY][k];
        a0.x = fmaf(x0, w4.x, a0.x); a0.y = fmaf(x0, w4.y, a0.y);
        a0.z = fmaf(x0, w4.z, a0.z); a0.w = fmaf(x0, w4.w, a0.w);
        a1.x = fmaf(x1, w4.x, a1.x); a1.y = fmaf(x1, w4.y, a1.y);
        a1.z = fmaf(x1, w4.z, a1.z); a1.w = fmaf(x1, w4.w, a1.w);
    }
    int n0 = nb + ty, n1 = nb + ty + TY;
    float s0 = g_dinv[n0], s1 = g_dinv[n1];
    a0.x *= s0; a0.y *= s0; a0.z *= s0; a0.w *= s0;
    a1.x *= s1; a1.y *= s1; a1.z *= s1; a1.w *= s1;
    *((float4*)&g_y2[n0 * 32 + tx * 4]) = a0;
    *((float4*)&g_y2[n1 * 32 + tx * 4]) = a1;
}

// ---- layer-2 aggregate + epilogue: out = dinv*(y2[d] + sum w*y2[s]) + b2 ----
__global__ void __launch_bounds__(256) k_agg2(const float* __restrict__ b2,
                                              float* __restrict__ out) {
    int warp = (blockIdx.x * 256 + threadIdx.x) >> 5;
    if (warp >= N) return;
    int lane = threadIdx.x & 31;
    int d = warp;
    int beg = g_rs[d], end = beg + g_cnt[d];
    float acc = g_y2[d * 32 + lane];           // self loop
    int j = beg;
    for (; j + 3 < end; j += 4) {
        int2 e0 = __ldg(&g_edge[j]),     e1 = __ldg(&g_edge[j + 1]);
        int2 e2 = __ldg(&g_edge[j + 2]), e3 = __ldg(&g_edge[j + 3]);
        float v0 = __ldg(&g_y2[e0.x * 32 + lane]);
        float v1 = __ldg(&g_y2[e1.x * 32 + lane]);
        float v2 = __ldg(&g_y2[e2.x * 32 + lane]);
        float v3 = __ldg(&g_y2[e3.x * 32 + lane]);
        acc = fmaf(__int_as_float(e0.y), v0, acc);
        acc = fmaf(__int_as_float(e1.y), v1, acc);
        acc = fmaf(__int_as_float(e2.y), v2, acc);
        acc = fmaf(__int_as_float(e3.y), v3, acc);
    }
    for (; j < end; j++) {
        int2 e = __ldg(&g_edge[j]);
        acc = fmaf(__int_as_float(e.y), __ldg(&g_y2[e.x * 32 + lane]), acc);
    }
    out[d * 32 + lane] = fmaf(g_dinv[d], acc, b2[lane]);
}

extern "C" void kernel_launch(void* const* d_in, const int* in_sizes, int n_in,
                              void* d_out, int out_size) {
    const float* x  = (const float*)d_in[0];
    const int*   ei = (const int*)d_in[1];     // edge_index as int32
    const float* ew = (const float*)d_in[2];
    const float* W1 = (const float*)d_in[3];
    const float* b1 = (const float*)d_in[4];
    const float* W2 = (const float*)d_in[5];
    const float* b2 = (const float*)d_in[6];
    float* out = (float*)d_out;

    void* p_cw = nullptr;
    cudaGetSymbolAddress(&p_cw, g_cw);
    cudaMemsetAsync(p_cw, 0, N * sizeof(unsigned long long));

    k_prep      <<<(E / 4 + 255) / 256, 256>>>(ei, ew);
    k_decode    <<<(N + 255) / 256, 256>>>();
    k_scan_block<<<NB_SCAN, SCAN_B>>>();
    k_scan_bsum <<<1, 256>>>();
    k_scan_fix  <<<(N + 255) / 256, 256>>>();
    k_reorder   <<<(E + 255) / 256, 256>>>(ei, ew);
    k_gemm1     <<<N / 32, dim3(16, 8)>>>(x, W1);
    k_agg1      <<<(N * 32 + 255) / 256, 256>>>(b1);
    k_gemm2     <<<N / 32, dim3(8, 16)>>>(W2);
    k_agg2      <<<(N * 32 + 255) / 256, 256>>>(b2, out);
}

// round 9
// speedup vs baseline: 1.8702x; 1.0820x over previous
#include <cuda_runtime.h>
#include <cuda_fp16.h>

static constexpr int N = 100000;
static constexpr int E = 1600000;
static constexpr int SCAN_B = 512;
static constexpr int NB_SCAN = (N + SCAN_B - 1) / SCAN_B;   // 196

// ---- device-global scratch ----
__device__ unsigned long long g_cw[N];  // packed: count<<40 | wdeg*2^24 (memset 0)
__device__ float   g_dinv[N];
__device__ int     g_cnt[N];
__device__ int     g_scan[N];
__device__ int     g_rs[N];
__device__ int     g_cur[N];
__device__ int     g_bsum[NB_SCAN];
__device__ int     g_boff[NB_SCAN];
__device__ int2    g_edge[E];           // {src, w*dinv[src] as bits}
__device__ __half2 g_y1h[N * 32];       // x @ W1, raw, fp16 (128 B/row)
__device__ float   g_h [N * 64];        // relu'd hidden, fp32
__device__ float   g_y2[N * 32];        // h @ W2, raw, fp32

// ---- count + weighted degree: one packed u64 atomic per edge, 4 edges/thread ----
__global__ void k_prep(const int* __restrict__ ei, const float* __restrict__ ew) {
    int t = blockIdx.x * blockDim.x + threadIdx.x;
    int e = t * 4;
    if (e >= E) return;
    int4   d4 = *((const int4*)(ei + E + e));
    float4 w4 = *((const float4*)(ew + e));
    #pragma unroll
    for (int k = 0; k < 4; k++) {
        int d = (&d4.x)[k];
        float w = (&w4.x)[k];
        if ((unsigned)d >= (unsigned)N) d = 0;
        unsigned long long v = (1ULL << 40) |
            (unsigned long long)(unsigned int)__float2uint_rn(w * 16777216.0f);
        atomicAdd(&g_cw[d], v);
    }
}

// ---- scan stage 1 (+ fused decode): per-block inclusive scan of counts ----
__global__ void __launch_bounds__(SCAN_B) k_scan_block() {
    __shared__ int wsum[16];
    int t = threadIdx.x, lane = t & 31, wid = t >> 5;
    int g = blockIdx.x * SCAN_B + t;
    int v = 0;
    if (g < N) {
        unsigned long long p = g_cw[g];
        v = (int)(p >> 40);
        float wdeg = (float)(p & ((1ULL << 40) - 1)) * (1.0f / 16777216.0f);
        g_cnt[g] = v;
        g_dinv[g] = rsqrtf(1.0f + wdeg);   // self loop contributes 1
    }
    int s = v;
    #pragma unroll
    for (int o = 1; o < 32; o <<= 1) {
        int n = __shfl_up_sync(0xffffffffu, s, o);
        if (lane >= o) s += n;
    }
    if (lane == 31) wsum[wid] = s;
    __syncthreads();
    if (wid == 0) {
        int ws = (lane < 16) ? wsum[lane] : 0;
        #pragma unroll
        for (int o = 1; o < 16; o <<= 1) {
            int n = __shfl_up_sync(0xffffffffu, ws, o);
            if (lane >= o) ws += n;
        }
        if (lane < 16) wsum[lane] = ws;
    }
    __syncthreads();
    int off = wid ? wsum[wid - 1] : 0;
    s += off;
    if (g < N) g_scan[g] = s;
    if (t == SCAN_B - 1) g_bsum[blockIdx.x] = s;
}

// ---- scan stage 2: exclusive scan of 196 block sums (one block) ----
__global__ void __launch_bounds__(256) k_scan_bsum() {
    __shared__ int wsum[8];
    int t = threadIdx.x, lane = t & 31, wid = t >> 5;
    int v = (t < NB_SCAN) ? g_bsum[t] : 0;
    int s = v;
    #pragma unroll
    for (int o = 1; o < 32; o <<= 1) {
        int n = __shfl_up_sync(0xffffffffu, s, o);
        if (lane >= o) s += n;
    }
    if (lane == 31) wsum[wid] = s;
    __syncthreads();
    if (wid == 0) {
        int ws = (lane < 8) ? wsum[lane] : 0;
        #pragma unroll
        for (int o = 1; o < 8; o <<= 1) {
            int n = __shfl_up_sync(0xffffffffu, ws, o);
            if (lane >= o) ws += n;
        }
        if (lane < 8) wsum[lane] = ws;
    }
    __syncthreads();
    int off = wid ? wsum[wid - 1] : 0;
    if (t < NB_SCAN) g_boff[t] = s + off - v;   // exclusive
}

// ---- scan stage 3: row starts + cursors ----
__global__ void k_scan_fix() {
    int i = blockIdx.x * blockDim.x + threadIdx.x;
    if (i >= N) return;
    int incl = g_scan[i] + g_boff[i / SCAN_B];
    int start = incl - g_cnt[i];
    g_rs[i]  = start;
    g_cur[i] = start;
}

// ---- bucket edges by destination, bake dinv[src] into the weight ----
__global__ void k_reorder(const int* __restrict__ ei, const float* __restrict__ ew) {
    int e = blockIdx.x * blockDim.x + threadIdx.x;
    if (e >= E) return;
    int s = ei[e];
    int d = ei[E + e];
    if ((unsigned)s >= (unsigned)N) s = 0;
    if ((unsigned)d >= (unsigned)N) d = 0;
    float wp = ew[e] * __ldg(&g_dinv[s]);
    int pos = atomicAdd(&g_cur[d], 1);
    g_edge[pos] = make_int2(s, __float_as_int(wp));
}

// ---- layer-1 GEMM: y1 = x @ W1 (raw, fp16 out). Independent of prep chain. ----
__global__ void __launch_bounds__(128) k_gemm1(const float* __restrict__ X,
                                               const float* __restrict__ W) {
    constexpr int TX = 16, NPB = 32;
    __shared__ float Ws[64 * 64];
    __shared__ float Xs[NPB][68];
    int tid = threadIdx.y * TX + threadIdx.x;
    {
        const float4* Wg = (const float4*)W;
        float4* Ws4 = (float4*)Ws;
        #pragma unroll
        for (int i = tid; i < 64 * 64 / 4; i += 128) Ws4[i] = Wg[i];
    }
    int nb = blockIdx.x * NPB;                 // N % 32 == 0
    #pragma unroll
    for (int i = tid; i < NPB * 16; i += 128) {
        int node = i >> 4, k4 = i & 15;
        *((float4*)&Xs[node][k4 * 4]) = ((const float4*)(X + (nb + node) * 64))[k4];
    }
    __syncthreads();

    int tx = threadIdx.x, ty = threadIdx.y;    // ty in 0..7
    float4 a0 = {0,0,0,0}, a1 = {0,0,0,0}, a2 = {0,0,0,0}, a3 = {0,0,0,0};
    #pragma unroll
    for (int k4 = 0; k4 < 16; k4++) {
        float4 xv0 = *((const float4*)&Xs[ty][k4 * 4]);
        float4 xv1 = *((const float4*)&Xs[ty + 8][k4 * 4]);
        float4 xv2 = *((const float4*)&Xs[ty + 16][k4 * 4]);
        float4 xv3 = *((const float4*)&Xs[ty + 24][k4 * 4]);
        #pragma unroll
        for (int kk = 0; kk < 4; kk++) {
            float4 w4 = *((const float4*)&Ws[(k4 * 4 + kk) * 64 + tx * 4]);
            float x0 = (&xv0.x)[kk], x1 = (&xv1.x)[kk];
            float x2 = (&xv2.x)[kk], x3 = (&xv3.x)[kk];
            a0.x = fmaf(x0, w4.x, a0.x); a0.y = fmaf(x0, w4.y, a0.y);
            a0.z = fmaf(x0, w4.z, a0.z); a0.w = fmaf(x0, w4.w, a0.w);
            a1.x = fmaf(x1, w4.x, a1.x); a1.y = fmaf(x1, w4.y, a1.y);
            a1.z = fmaf(x1, w4.z, a1.z); a1.w = fmaf(x1, w4.w, a1.w);
            a2.x = fmaf(x2, w4.x, a2.x); a2.y = fmaf(x2, w4.y, a2.y);
            a2.z = fmaf(x2, w4.z, a2.z); a2.w = fmaf(x2, w4.w, a2.w);
            a3.x = fmaf(x3, w4.x, a3.x); a3.y = fmaf(x3, w4.y, a3.y);
            a3.z = fmaf(x3, w4.z, a3.z); a3.w = fmaf(x3, w4.w, a3.w);
        }
    }
    #pragma unroll
    for (int m = 0; m < 4; m++) {
        int n = nb + ty + 8 * m;
        float4 a = (m == 0) ? a0 : (m == 1) ? a1 : (m == 2) ? a2 : a3;
        __half2 h0 = __floats2half2_rn(a.x, a.y);
        __half2 h1 = __floats2half2_rn(a.z, a.w);
        *((__half2*)&g_y1h[n * 32 + tx * 2])     = h0;
        *((__half2*)&g_y1h[n * 32 + tx * 2 + 1]) = h1;
    }
}

// ---- layer-1 aggregate (warp per node):
//      h = relu(dinv*(dinv*y1[d] + sum w'*y1[s]) + b1), y1 gathered in fp16 ----
__global__ void __launch_bounds__(256) k_agg1(const float* __restrict__ b1) {
    int warp = (blockIdx.x * 256 + threadIdx.x) >> 5;
    if (warp >= N) return;
    int lane = threadIdx.x & 31;
    int d = warp;
    int beg = g_rs[d], end = beg + g_cnt[d];
    float di = g_dinv[d];
    float2 self = __half22float2(g_y1h[d * 32 + lane]);
    float2 acc;
    acc.x = di * self.x; acc.y = di * self.y;
    int j = beg;
    for (; j + 3 < end; j += 4) {
        int2 e0 = __ldg(&g_edge[j]),     e1 = __ldg(&g_edge[j + 1]);
        int2 e2 = __ldg(&g_edge[j + 2]), e3 = __ldg(&g_edge[j + 3]);
        float2 v0 = __half22float2(__ldg(&g_y1h[e0.x * 32 + lane]));
        float2 v1 = __half22float2(__ldg(&g_y1h[e1.x * 32 + lane]));
        float2 v2 = __half22float2(__ldg(&g_y1h[e2.x * 32 + lane]));
        float2 v3 = __half22float2(__ldg(&g_y1h[e3.x * 32 + lane]));
        float w0 = __int_as_float(e0.y), w1 = __int_as_float(e1.y);
        float w2 = __int_as_float(e2.y), w3 = __int_as_float(e3.y);
        acc.x = fmaf(w0, v0.x, acc.x); acc.y = fmaf(w0, v0.y, acc.y);
        acc.x = fmaf(w1, v1.x, acc.x); acc.y = fmaf(w1, v1.y, acc.y);
        acc.x = fmaf(w2, v2.x, acc.x); acc.y = fmaf(w2, v2.y, acc.y);
        acc.x = fmaf(w3, v3.x, acc.x); acc.y = fmaf(w3, v3.y, acc.y);
    }
    for (; j < end; j++) {
        int2 e = __ldg(&g_edge[j]);
        float w = __int_as_float(e.y);
        float2 v = __half22float2(__ldg(&g_y1h[e.x * 32 + lane]));
        acc.x = fmaf(w, v.x, acc.x); acc.y = fmaf(w, v.y, acc.y);
    }
    float2 h;
    h.x = fmaxf(fmaf(di, acc.x, __ldg(&b1[lane * 2])), 0.0f);
    h.y = fmaxf(fmaf(di, acc.y, __ldg(&b1[lane * 2 + 1])), 0.0f);
    *((float2*)&g_h[d * 64 + lane * 2]) = h;
}

// ---- layer-2 GEMM: y2 = h @ W2 (raw) ----
__global__ void __launch_bounds__(128) k_gemm2(const float* __restrict__ W2) {
    constexpr int TX = 8, TY = 16, NPB = 32;
    __shared__ float Ws[64 * 32];
    __shared__ float Xs[NPB][68];
    int tid = threadIdx.y * TX + threadIdx.x;
    {
        const float4* Wg = (const float4*)W2;
        float4* Ws4 = (float4*)Ws;
        #pragma unroll
        for (int i = tid; i < 64 * 32 / 4; i += 128) Ws4[i] = Wg[i];
    }
    int nb = blockIdx.x * NPB;
    #pragma unroll
    for (int i = tid; i < NPB * 16; i += 128) {
        int node = i >> 4, k4 = i & 15;
        *((float4*)&Xs[node][k4 * 4]) = ((const float4*)&g_h[(nb + node) * 64])[k4];
    }
    __syncthreads();

    int tx = threadIdx.x, ty = threadIdx.y;
    float4 a0 = {0,0,0,0}, a1 = {0,0,0,0};
    #pragma unroll
    for (int k = 0; k < 64; k++) {
        float4 w4 = *((const float4*)&Ws[k * 32 + tx * 4]);
        float x0 = Xs[ty][k], x1 = Xs[ty + TY][k];
        a0.x = fmaf(x0, w4.x, a0.x); a0.y = fmaf(x0, w4.y, a0.y);
        a0.z = fmaf(x0, w4.z, a0.z); a0.w = fmaf(x0, w4.w, a0.w);
        a1.x = fmaf(x1, w4.x, a1.x); a1.y = fmaf(x1, w4.y, a1.y);
        a1.z = fmaf(x1, w4.z, a1.z); a1.w = fmaf(x1, w4.w, a1.w);
    }
    int n0 = nb + ty, n1 = nb + ty + TY;
    *((float4*)&g_y2[n0 * 32 + tx * 4]) = a0;
    *((float4*)&g_y2[n1 * 32 + tx * 4]) = a1;
}

// ---- layer-2 aggregate + epilogue: out = dinv*(dinv*y2[d] + sum w'*y2[s]) + b2 ----
__global__ void __launch_bounds__(256) k_agg2(const float* __restrict__ b2,
                                              float* __restrict__ out) {
    int warp = (blockIdx.x * 256 + threadIdx.x) >> 5;
    if (warp >= N) return;
    int lane = threadIdx.x & 31;
    int d = warp;
    int beg = g_rs[d], end = beg + g_cnt[d];
    float di = g_dinv[d];
    float acc = di * g_y2[d * 32 + lane];      // self loop
    int j = beg;
    for (; j + 3 < end; j += 4) {
        int2 e0 = __ldg(&g_edge[j]),     e1 = __ldg(&g_edge[j + 1]);
        int2 e2 = __ldg(&g_edge[j + 2]), e3 = __ldg(&g_edge[j + 3]);
        float v0 = __ldg(&g_y2[e0.x * 32 + lane]);
        float v1 = __ldg(&g_y2[e1.x * 32 + lane]);
        float v2 = __ldg(&g_y2[e2.x * 32 + lane]);
        float v3 = __ldg(&g_y2[e3.x * 32 + lane]);
        acc = fmaf(__int_as_float(e0.y), v0, acc);
        acc = fmaf(__int_as_float(e1.y), v1, acc);
        acc = fmaf(__int_as_float(e2.y), v2, acc);
        acc = fmaf(__int_as_float(e3.y), v3, acc);
    }
    for (; j < end; j++) {
        int2 e = __ldg(&g_edge[j]);
        acc = fmaf(__int_as_float(e.y), __ldg(&g_y2[e.x * 32 + lane]), acc);
    }
    out[d * 32 + lane] = fmaf(di, acc, b2[lane]);
}

extern "C" void kernel_launch(void* const* d_in, const int* in_sizes, int n_in,
                              void* d_out, int out_size) {
    const float* x  = (const float*)d_in[0];
    const int*   ei = (const int*)d_in[1];     // edge_index as int32
    const float* ew = (const float*)d_in[2];
    const float* W1 = (const float*)d_in[3];
    const float* b1 = (const float*)d_in[4];
    const float* W2 = (const float*)d_in[5];
    const float* b2 = (const float*)d_in[6];
    float* out = (float*)d_out;

    // side stream for gemm1 (independent of the prep chain). Handles are
    // created per call and intentionally not destroyed: kernel_launch runs
    // only a handful of times (correctness + capture), and destroying
    // capture-participating handles mid-capture is the riskier path.
    cudaStream_t s2;
    cudaStreamCreateWithFlags(&s2, cudaStreamNonBlocking);
    cudaEvent_t ev_fork, ev_join;
    cudaEventCreateWithFlags(&ev_fork, cudaEventDisableTiming);
    cudaEventCreateWithFlags(&ev_join, cudaEventDisableTiming);

    // fork: gemm1 on s2, depends only on inputs
    cudaEventRecord(ev_fork, 0);
    cudaStreamWaitEvent(s2, ev_fork, 0);
    k_gemm1<<<N / 32, dim3(16, 8), 0, s2>>>(x, W1);
    cudaEventRecord(ev_join, s2);

    // main chain
    void* p_cw = nullptr;
    cudaGetSymbolAddress(&p_cw, g_cw);
    cudaMemsetAsync(p_cw, 0, N * sizeof(unsigned long long));
    k_prep      <<<(E / 4 + 255) / 256, 256>>>(ei, ew);
    k_scan_block<<<NB_SCAN, SCAN_B>>>();
    k_scan_bsum <<<1, 256>>>();
    k_scan_fix  <<<(N + 255) / 256, 256>>>();
    k_reorder   <<<(E + 255) / 256, 256>>>(ei, ew);

    // join: agg1 needs both reorder (main) and gemm1 (s2)
    cudaStreamWaitEvent(0, ev_join, 0);
    k_agg1      <<<(N * 32 + 255) / 256, 256>>>(b1);
    k_gemm2     <<<N / 32, dim3(8, 16)>>>(W2);
    k_agg2      <<<(N * 32 + 255) / 256, 256>>>(b2, out);
}

// round 10
// speedup vs baseline: 1.8951x; 1.0133x over previous
#include <cuda_runtime.h>
#include <cuda_fp16.h>

static constexpr int N = 100000;
static constexpr int E = 1600000;
static constexpr int SCAN_B = 512;
static constexpr int NB_SCAN = (N + SCAN_B - 1) / SCAN_B;   // 196

// ---- zeroed-per-launch region (single memset): g_cw[N] | g_state[NB] | ticket ----
__device__ unsigned long long g_zero[N + NB_SCAN + 1];
#define g_cw     (g_zero)                  // packed: count<<40 | wdeg*2^24
#define g_state  (g_zero + N)              // lookback: flag<<62 | inclusive/aggregate
#define g_ticket (g_zero + N + NB_SCAN)

__device__ float   g_dinv[N];
__device__ int     g_cnt[N];
__device__ int     g_rs[N];
__device__ int     g_cur[N];
__device__ int2    g_edge[E];              // {src, w*dinv[src] as bits}
__device__ __half2 g_y1h[N * 32];          // x @ W1, raw, fp16 (128 B/row)
__device__ float   g_h [N * 64];           // relu'd hidden, fp32
__device__ __half2 g_y2h[N * 16];          // h @ W2, raw, fp16 (64 B/row)

// ---- count + weighted degree: one packed u64 atomic per edge, 4 edges/thread ----
__global__ void k_prep(const int* __restrict__ ei, const float* __restrict__ ew) {
    int t = blockIdx.x * blockDim.x + threadIdx.x;
    int e = t * 4;
    if (e >= E) return;
    int4   d4 = *((const int4*)(ei + E + e));
    float4 w4 = *((const float4*)(ew + e));
    #pragma unroll
    for (int k = 0; k < 4; k++) {
        int d = (&d4.x)[k];
        float w = (&w4.x)[k];
        if ((unsigned)d >= (unsigned)N) d = 0;
        unsigned long long v = (1ULL << 40) |
            (unsigned long long)(unsigned int)__float2uint_rn(w * 16777216.0f);
        atomicAdd(&g_cw[d], v);
    }
}

// ---- single-kernel scan: decode + decoupled-lookback prefix + rs/cur/dinv ----
__global__ void __launch_bounds__(SCAN_B) k_scan() {
    __shared__ int wsum[16];
    __shared__ int sh_bid;
    __shared__ unsigned sh_excl;
    __shared__ int sh_total;
    int t = threadIdx.x, lane = t & 31, wid = t >> 5;

    if (t == 0) sh_bid = (int)atomicAdd(g_ticket, 1ULL);   // ordered tile id
    __syncthreads();
    int bid = sh_bid;
    int g = bid * SCAN_B + t;

    // decode count + dinv
    int v = 0;
    if (g < N) {
        unsigned long long p = g_cw[g];
        v = (int)(p >> 40);
        float wdeg = (float)(p & ((1ULL << 40) - 1)) * (1.0f / 16777216.0f);
        g_cnt[g] = v;
        g_dinv[g] = rsqrtf(1.0f + wdeg);
    }
    // block-local inclusive scan
    int s = v;
    #pragma unroll
    for (int o = 1; o < 32; o <<= 1) {
        int n = __shfl_up_sync(0xffffffffu, s, o);
        if (lane >= o) s += n;
    }
    if (lane == 31) wsum[wid] = s;
    __syncthreads();
    if (wid == 0) {
        int ws = (lane < 16) ? wsum[lane] : 0;
        #pragma unroll
        for (int o = 1; o < 16; o <<= 1) {
            int n = __shfl_up_sync(0xffffffffu, ws, o);
            if (lane >= o) ws += n;
        }
        if (lane < 16) wsum[lane] = ws;
    }
    __syncthreads();
    s += wid ? wsum[wid - 1] : 0;
    if (t == SCAN_B - 1) sh_total = s;
    __syncthreads();
    int total = sh_total;

    // warp 0: publish + lookback
    if (wid == 0) {
        if (lane == 0) {
            unsigned long long pub = (bid == 0)
                ? ((2ULL << 62) | (unsigned)total)       // inclusive ready
                : ((1ULL << 62) | (unsigned)total);      // aggregate ready
            atomicExch(&g_state[bid], pub);
        }
        __syncwarp();
        unsigned running = 0;
        if (bid > 0) {
            int idx = bid - 1;
            while (true) {
                int look = idx - lane;
                unsigned long long st = 0;
                if (look >= 0) {
                    do { st = atomicAdd(&g_state[look], 0ULL); }
                    while ((st >> 62) == 0);
                }
                unsigned flag = (unsigned)(st >> 62);
                unsigned val = (unsigned)(st & 0xffffffffu);
                unsigned mask_inc = __ballot_sync(0xffffffffu, look >= 0 && flag == 2u);
                if (mask_inc) {
                    int firstInc = __ffs(mask_inc) - 1;  // nearest predecessor w/ inclusive
                    unsigned c = (look >= 0 && lane <= firstInc) ? val : 0;
                    #pragma unroll
                    for (int o = 16; o > 0; o >>= 1) c += __shfl_down_sync(0xffffffffu, c, o);
                    running += __shfl_sync(0xffffffffu, c, 0);
                    break;
                } else {
                    unsigned c = (look >= 0) ? val : 0;
                    #pragma unroll
                    for (int o = 16; o > 0; o >>= 1) c += __shfl_down_sync(0xffffffffu, c, o);
                    running += __shfl_sync(0xffffffffu, c, 0);
                    idx -= 32;
                    if (idx < 0) break;
                }
            }
            if (lane == 0)
                atomicExch(&g_state[bid], (2ULL << 62) | (unsigned)(running + total));
        }
        if (lane == 0) sh_excl = running;
    }
    __syncthreads();
    int excl = (int)sh_excl;

    if (g < N) {
        int start = excl + s - v;   // exclusive global prefix
        g_rs[g]  = start;
        g_cur[g] = start;
    }
}

// ---- bucket edges by destination, bake dinv[src] into the weight ----
__global__ void k_reorder(const int* __restrict__ ei, const float* __restrict__ ew) {
    int e = blockIdx.x * blockDim.x + threadIdx.x;
    if (e >= E) return;
    int s = ei[e];
    int d = ei[E + e];
    if ((unsigned)s >= (unsigned)N) s = 0;
    if ((unsigned)d >= (unsigned)N) d = 0;
    float wp = ew[e] * __ldg(&g_dinv[s]);
    int pos = atomicAdd(&g_cur[d], 1);
    g_edge[pos] = make_int2(s, __float_as_int(wp));
}

// ---- layer-1 GEMM: y1 = x @ W1 (raw, fp16 out). Independent of prep chain. ----
__global__ void __launch_bounds__(128) k_gemm1(const float* __restrict__ X,
                                               const float* __restrict__ W) {
    constexpr int TX = 16, NPB = 32;
    __shared__ float Ws[64 * 64];
    __shared__ float Xs[NPB][68];
    int tid = threadIdx.y * TX + threadIdx.x;
    {
        const float4* Wg = (const float4*)W;
        float4* Ws4 = (float4*)Ws;
        #pragma unroll
        for (int i = tid; i < 64 * 64 / 4; i += 128) Ws4[i] = Wg[i];
    }
    int nb = blockIdx.x * NPB;                 // N % 32 == 0
    #pragma unroll
    for (int i = tid; i < NPB * 16; i += 128) {
        int node = i >> 4, k4 = i & 15;
        *((float4*)&Xs[node][k4 * 4]) = ((const float4*)(X + (nb + node) * 64))[k4];
    }
    __syncthreads();

    int tx = threadIdx.x, ty = threadIdx.y;    // ty in 0..7
    float4 a0 = {0,0,0,0}, a1 = {0,0,0,0}, a2 = {0,0,0,0}, a3 = {0,0,0,0};
    #pragma unroll
    for (int k4 = 0; k4 < 16; k4++) {
        float4 xv0 = *((const float4*)&Xs[ty][k4 * 4]);
        float4 xv1 = *((const float4*)&Xs[ty + 8][k4 * 4]);
        float4 xv2 = *((const float4*)&Xs[ty + 16][k4 * 4]);
        float4 xv3 = *((const float4*)&Xs[ty + 24][k4 * 4]);
        #pragma unroll
        for (int kk = 0; kk < 4; kk++) {
            float4 w4 = *((const float4*)&Ws[(k4 * 4 + kk) * 64 + tx * 4]);
            float x0 = (&xv0.x)[kk], x1 = (&xv1.x)[kk];
            float x2 = (&xv2.x)[kk], x3 = (&xv3.x)[kk];
            a0.x = fmaf(x0, w4.x, a0.x); a0.y = fmaf(x0, w4.y, a0.y);
            a0.z = fmaf(x0, w4.z, a0.z); a0.w = fmaf(x0, w4.w, a0.w);
            a1.x = fmaf(x1, w4.x, a1.x); a1.y = fmaf(x1, w4.y, a1.y);
            a1.z = fmaf(x1, w4.z, a1.z); a1.w = fmaf(x1, w4.w, a1.w);
            a2.x = fmaf(x2, w4.x, a2.x); a2.y = fmaf(x2, w4.y, a2.y);
            a2.z = fmaf(x2, w4.z, a2.z); a2.w = fmaf(x2, w4.w, a2.w);
            a3.x = fmaf(x3, w4.x, a3.x); a3.y = fmaf(x3, w4.y, a3.y);
            a3.z = fmaf(x3, w4.z, a3.z); a3.w = fmaf(x3, w4.w, a3.w);
        }
    }
    #pragma unroll
    for (int m = 0; m < 4; m++) {
        int n = nb + ty + 8 * m;
        float4 a = (m == 0) ? a0 : (m == 1) ? a1 : (m == 2) ? a2 : a3;
        *((__half2*)&g_y1h[n * 32 + tx * 2])     = __floats2half2_rn(a.x, a.y);
        *((__half2*)&g_y1h[n * 32 + tx * 2 + 1]) = __floats2half2_rn(a.z, a.w);
    }
}

// ---- layer-1 aggregate (warp per node), y1 gathered in fp16 ----
__global__ void __launch_bounds__(256) k_agg1(const float* __restrict__ b1) {
    int warp = (blockIdx.x * 256 + threadIdx.x) >> 5;
    if (warp >= N) return;
    int lane = threadIdx.x & 31;
    int d = warp;
    int beg = g_rs[d], end = beg + g_cnt[d];
    float di = g_dinv[d];
    float2 self = __half22float2(g_y1h[d * 32 + lane]);
    float2 acc;
    acc.x = di * self.x; acc.y = di * self.y;
    int j = beg;
    for (; j + 3 < end; j += 4) {
        int2 e0 = __ldg(&g_edge[j]),     e1 = __ldg(&g_edge[j + 1]);
        int2 e2 = __ldg(&g_edge[j + 2]), e3 = __ldg(&g_edge[j + 3]);
        float2 v0 = __half22float2(__ldg(&g_y1h[e0.x * 32 + lane]));
        float2 v1 = __half22float2(__ldg(&g_y1h[e1.x * 32 + lane]));
        float2 v2 = __half22float2(__ldg(&g_y1h[e2.x * 32 + lane]));
        float2 v3 = __half22float2(__ldg(&g_y1h[e3.x * 32 + lane]));
        float w0 = __int_as_float(e0.y), w1 = __int_as_float(e1.y);
        float w2 = __int_as_float(e2.y), w3 = __int_as_float(e3.y);
        acc.x = fmaf(w0, v0.x, acc.x); acc.y = fmaf(w0, v0.y, acc.y);
        acc.x = fmaf(w1, v1.x, acc.x); acc.y = fmaf(w1, v1.y, acc.y);
        acc.x = fmaf(w2, v2.x, acc.x); acc.y = fmaf(w2, v2.y, acc.y);
        acc.x = fmaf(w3, v3.x, acc.x); acc.y = fmaf(w3, v3.y, acc.y);
    }
    for (; j < end; j++) {
        int2 e = __ldg(&g_edge[j]);
        float w = __int_as_float(e.y);
        float2 v = __half22float2(__ldg(&g_y1h[e.x * 32 + lane]));
        acc.x = fmaf(w, v.x, acc.x); acc.y = fmaf(w, v.y, acc.y);
    }
    float2 h;
    h.x = fmaxf(fmaf(di, acc.x, __ldg(&b1[lane * 2])), 0.0f);
    h.y = fmaxf(fmaf(di, acc.y, __ldg(&b1[lane * 2 + 1])), 0.0f);
    *((float2*)&g_h[d * 64 + lane * 2]) = h;
}

// ---- layer-2 GEMM: y2 = h @ W2 (raw, fp16 out) ----
__global__ void __launch_bounds__(128) k_gemm2(const float* __restrict__ W2) {
    constexpr int TX = 8, TY = 16, NPB = 32;
    __shared__ float Ws[64 * 32];
    __shared__ float Xs[NPB][68];
    int tid = threadIdx.y * TX + threadIdx.x;
    {
        const float4* Wg = (const float4*)W2;
        float4* Ws4 = (float4*)Ws;
        #pragma unroll
        for (int i = tid; i < 64 * 32 / 4; i += 128) Ws4[i] = Wg[i];
    }
    int nb = blockIdx.x * NPB;
    #pragma unroll
    for (int i = tid; i < NPB * 16; i += 128) {
        int node = i >> 4, k4 = i & 15;
        *((float4*)&Xs[node][k4 * 4]) = ((const float4*)&g_h[(nb + node) * 64])[k4];
    }
    __syncthreads();

    int tx = threadIdx.x, ty = threadIdx.y;
    float4 a0 = {0,0,0,0}, a1 = {0,0,0,0};
    #pragma unroll
    for (int k = 0; k < 64; k++) {
        float4 w4 = *((const float4*)&Ws[k * 32 + tx * 4]);
        float x0 = Xs[ty][k], x1 = Xs[ty + TY][k];
        a0.x = fmaf(x0, w4.x, a0.x); a0.y = fmaf(x0, w4.y, a0.y);
        a0.z = fmaf(x0, w4.z, a0.z); a0.w = fmaf(x0, w4.w, a0.w);
        a1.x = fmaf(x1, w4.x, a1.x); a1.y = fmaf(x1, w4.y, a1.y);
        a1.z = fmaf(x1, w4.z, a1.z); a1.w = fmaf(x1, w4.w, a1.w);
    }
    int n0 = nb + ty, n1 = nb + ty + TY;
    *((__half2*)&g_y2h[n0 * 16 + tx * 2])     = __floats2half2_rn(a0.x, a0.y);
    *((__half2*)&g_y2h[n0 * 16 + tx * 2 + 1]) = __floats2half2_rn(a0.z, a0.w);
    *((__half2*)&g_y2h[n1 * 16 + tx * 2])     = __floats2half2_rn(a1.x, a1.y);
    *((__half2*)&g_y2h[n1 * 16 + tx * 2 + 1]) = __floats2half2_rn(a1.z, a1.w);
}

// ---- layer-2 aggregate + epilogue, y2 gathered in fp16 ----
__global__ void __launch_bounds__(256) k_agg2(const float* __restrict__ b2,
                                              float* __restrict__ out) {
    const __half* y2 = (const __half*)g_y2h;
    int warp = (blockIdx.x * 256 + threadIdx.x) >> 5;
    if (warp >= N) return;
    int lane = threadIdx.x & 31;
    int d = warp;
    int beg = g_rs[d], end = beg + g_cnt[d];
    float di = g_dinv[d];
    float acc = di * __half2float(y2[d * 32 + lane]);   // self loop
    int j = beg;
    for (; j + 3 < end; j += 4) {
        int2 e0 = __ldg(&g_edge[j]),     e1 = __ldg(&g_edge[j + 1]);
        int2 e2 = __ldg(&g_edge[j + 2]), e3 = __ldg(&g_edge[j + 3]);
        float v0 = __half2float(__ldg(&y2[e0.x * 32 + lane]));
        float v1 = __half2float(__ldg(&y2[e1.x * 32 + lane]));
        float v2 = __half2float(__ldg(&y2[e2.x * 32 + lane]));
        float v3 = __half2float(__ldg(&y2[e3.x * 32 + lane]));
        acc = fmaf(__int_as_float(e0.y), v0, acc);
        acc = fmaf(__int_as_float(e1.y), v1, acc);
        acc = fmaf(__int_as_float(e2.y), v2, acc);
        acc = fmaf(__int_as_float(e3.y), v3, acc);
    }
    for (; j < end; j++) {
        int2 e = __ldg(&g_edge[j]);
        acc = fmaf(__int_as_float(e.y), __half2float(__ldg(&y2[e.x * 32 + lane])), acc);
    }
    out[d * 32 + lane] = fmaf(di, acc, b2[lane]);
}

extern "C" void kernel_launch(void* const* d_in, const int* in_sizes, int n_in,
                              void* d_out, int out_size) {
    const float* x  = (const float*)d_in[0];
    const int*   ei = (const int*)d_in[1];     // edge_index as int32
    const float* ew = (const float*)d_in[2];
    const float* W1 = (const float*)d_in[3];
    const float* b1 = (const float*)d_in[4];
    const float* W2 = (const float*)d_in[5];
    const float* b2 = (const float*)d_in[6];
    float* out = (float*)d_out;

    // side stream for gemm1 (independent of the prep chain)
    cudaStream_t s2;
    cudaStreamCreateWithFlags(&s2, cudaStreamNonBlocking);
    cudaEvent_t ev_fork, ev_join;
    cudaEventCreateWithFlags(&ev_fork, cudaEventDisableTiming);
    cudaEventCreateWithFlags(&ev_join, cudaEventDisableTiming);

    cudaEventRecord(ev_fork, 0);
    cudaStreamWaitEvent(s2, ev_fork, 0);
    k_gemm1<<<N / 32, dim3(16, 8), 0, s2>>>(x, W1);
    cudaEventRecord(ev_join, s2);

    // main chain
    void* p_zero = nullptr;
    cudaGetSymbolAddress(&p_zero, g_zero);
    cudaMemsetAsync(p_zero, 0, (N + NB_SCAN + 1) * sizeof(unsigned long long));
    k_prep   <<<(E / 4 + 255) / 256, 256>>>(ei, ew);
    k_scan   <<<NB_SCAN, SCAN_B>>>();
    k_reorder<<<(E + 255) / 256, 256>>>(ei, ew);

    cudaStreamWaitEvent(0, ev_join, 0);
    k_agg1   <<<(N * 32 + 255) / 256, 256>>>(b1);
    k_gemm2  <<<N / 32, dim3(8, 16)>>>(W2);
    k_agg2   <<<(N * 32 + 255) / 256, 256>>>(b2, out);
}